// round 7
// baseline (speedup 1.0000x reference)
#include <cuda_runtime.h>
#include <math.h>
#include <float.h>

// ---------------- problem constants ----------------
// BT=192, NQ=64, NC=1024, C=384, H=8, DH=48, HID=1536
#define QROWS   12288      /* BT*NQ            */
#define CROWS   196608     /* BT*NC            */
#define CDIM    384
#define HEADS   8
#define DHEAD   48
#define HIDDEN  1536
#define ATT_SCALE 0.14433756729740643f  /* 48^-0.5 */

// ---------------- scratch (device globals; no allocations allowed) -------
__device__ float g_xn [QROWS * CDIM];            //  18.9 MB
__device__ float g_cn [CROWS * CDIM];            // 302   MB
__device__ float g_q  [QROWS * CDIM];            //  18.9 MB
__device__ float g_kv [CROWS * 2 * CDIM];        // 604   MB
__device__ float g_o  [QROWS * CDIM];            //  18.9 MB
__device__ float g_xn2[QROWS * CDIM];            //  18.9 MB
__device__ float g_h  [QROWS * HIDDEN];          //  75.5 MB
__device__ int   g_mask_is_u8;                   // mask dtype flag

// ---------------- mask dtype detection ----------------
// If the mask buffer holds 4-byte elements with values {0,1} / {0.0f,1.0f},
// every byte at index%4==1 is zero. If it holds 1-byte bools, ~half of those
// 3072 positions are 1. One block, deterministic.
__global__ void detect_mask_kernel(const unsigned char* __restrict__ m)
{
    __shared__ int any;
    if (threadIdx.x == 0) any = 0;
    __syncthreads();
    int local = 0;
    for (int i = threadIdx.x; i < QROWS / 4; i += blockDim.x)
        if (m[4 * i + 1]) local = 1;
    if (local) atomicOr(&any, 1);
    __syncthreads();
    if (threadIdx.x == 0) g_mask_is_u8 = any;
}

// ---------------- LayerNorm over 384 cols, 1 block/row ----------------
__global__ __launch_bounds__(128) void ln384_kernel(
    const float* __restrict__ in, float* __restrict__ out,
    const float* __restrict__ gamma, const float* __restrict__ beta, float eps)
{
    size_t row = blockIdx.x;
    int t = threadIdx.x;
    const float* p = in + row * CDIM;
    float v0 = p[t], v1 = p[t + 128], v2 = p[t + 256];
    float s = v0 + v1 + v2;

    __shared__ float red[4];
    int lane = t & 31, warp = t >> 5;
    #pragma unroll
    for (int o = 16; o > 0; o >>= 1) s += __shfl_xor_sync(0xffffffffu, s, o);
    if (lane == 0) red[warp] = s;
    __syncthreads();
    float mean = (red[0] + red[1] + red[2] + red[3]) * (1.0f / 384.0f);

    float d0 = v0 - mean, d1 = v1 - mean, d2 = v2 - mean;
    float q = d0 * d0 + d1 * d1 + d2 * d2;
    #pragma unroll
    for (int o = 16; o > 0; o >>= 1) q += __shfl_xor_sync(0xffffffffu, q, o);
    __syncthreads();                    // everyone done reading red[]
    if (lane == 0) red[warp] = q;
    __syncthreads();
    float var = (red[0] + red[1] + red[2] + red[3]) * (1.0f / 384.0f);
    float rstd = rsqrtf(var + eps);

    float* po = out + row * CDIM;
    if (gamma) {
        po[t]       = d0 * rstd * gamma[t]       + beta[t];
        po[t + 128] = d1 * rstd * gamma[t + 128] + beta[t + 128];
        po[t + 256] = d2 * rstd * gamma[t + 256] + beta[t + 256];
    } else {
        po[t]       = d0 * rstd;
        po[t + 128] = d1 * rstd;
        po[t + 256] = d2 * rstd;
    }
}

// ---------------- GELU (tanh approx) ----------------
__device__ __forceinline__ float gelu_tanh(float x)
{
    float u = 0.7978845608028654f * (x + 0.044715f * x * x * x);
    return 0.5f * x * (1.0f + tanhf(u));
}

// ---------------- fp32 tiled GEMM: C = A(MxK) @ B(KxN) + bias [+gelu|+res] --
// 128x128 block tile, BK=8, 256 threads, 8x8 per-thread micro-tile.
// EPI: 0 = bias only, 1 = bias + gelu, 2 = bias + residual add
template <int EPI>
__global__ __launch_bounds__(256) void gemm_kernel(
    const float* __restrict__ A, const float* __restrict__ B,
    const float* __restrict__ bias, const float* __restrict__ res,
    float* __restrict__ Cm, int M, int N, int K)
{
    __shared__ float As[8][128];
    __shared__ float Bs[8][128];

    int t  = threadIdx.x;
    int m0 = blockIdx.y * 128, n0 = blockIdx.x * 128;
    int arow = t >> 1,  acol = (t & 1) * 4;     // A tile: 128x8
    int brow = t >> 5,  bcol = (t & 31) * 4;    // B tile: 8x128
    int tx = t & 15, ty = t >> 4;

    float acc[8][8] = {};
    const float* Aptr = A + (size_t)(m0 + arow) * K + acol;
    const float* Bptr = B + (size_t)brow * N + n0 + bcol;

    for (int k0 = 0; k0 < K; k0 += 8) {
        float4 av = *(const float4*)(Aptr + k0);
        As[acol + 0][arow] = av.x;
        As[acol + 1][arow] = av.y;
        As[acol + 2][arow] = av.z;
        As[acol + 3][arow] = av.w;
        float4 bv = *(const float4*)(Bptr + (size_t)k0 * N);
        *(float4*)&Bs[brow][bcol] = bv;
        __syncthreads();

        #pragma unroll
        for (int k = 0; k < 8; k++) {
            float4 a0 = *(const float4*)&As[k][ty * 8];
            float4 a1 = *(const float4*)&As[k][ty * 8 + 4];
            float4 b0 = *(const float4*)&Bs[k][tx * 8];
            float4 b1 = *(const float4*)&Bs[k][tx * 8 + 4];
            float ar[8] = {a0.x, a0.y, a0.z, a0.w, a1.x, a1.y, a1.z, a1.w};
            float br[8] = {b0.x, b0.y, b0.z, b0.w, b1.x, b1.y, b1.z, b1.w};
            #pragma unroll
            for (int i = 0; i < 8; i++)
                #pragma unroll
                for (int j = 0; j < 8; j++)
                    acc[i][j] += ar[i] * br[j];
        }
        __syncthreads();
    }

    #pragma unroll
    for (int i = 0; i < 8; i++) {
        int row = m0 + ty * 8 + i;
        #pragma unroll
        for (int j = 0; j < 8; j++) {
            int col = n0 + tx * 8 + j;
            float v = acc[i][j] + bias[col];
            if (EPI == 1) v = gelu_tanh(v);
            if (EPI == 2) v += res[(size_t)row * N + col];
            Cm[(size_t)row * N + col] = v;
        }
    }
}

// ---------------- flash attention: 1 block per (b, h) ----------------
// 256 threads; query row qi = t/4 owned by 4 threads, each holding 12 of 48 dims.
// Key tiles of 32. Masked-out rows => uniform attention (matches reference's
// fp32-absorbed -FLT_MAX bias exactly).
__global__ __launch_bounds__(256) void attn_kernel(
    const float* __restrict__ q, const float* __restrict__ kv,
    const void* __restrict__ mask, float* __restrict__ o)
{
    int b = blockIdx.x >> 3;   // / HEADS
    int h = blockIdx.x & 7;
    int t = threadIdx.x;

    __shared__ float qs[64][48];
    __shared__ float ks[32][48];
    __shared__ float vs[32][48];
    __shared__ float ss[64][32];

    #pragma unroll
    for (int i = 0; i < 12; i++) {              // 64*48 = 3072 = 256*12
        int idx = t + i * 256;
        int qi = idx / 48, d = idx % 48;
        qs[qi][d] = q[(size_t)(b * 64 + qi) * CDIM + h * 48 + d] * ATT_SCALE;
    }
    __syncthreads();

    int qi    = t >> 2;
    int quad  = t & 3;
    int dbase = quad * 12;

    // dtype-robust mask read: 1-byte bool vs 4-byte (int32 / float32 — both
    // have all-zero bits for false, nonzero bits for true).
    bool keep;
    {
        int mi = b * 64 + qi;
        if (g_mask_is_u8) keep = ((const unsigned char*)mask)[mi] != 0;
        else              keep = ((const int*)mask)[mi] != 0;
    }

    float qreg[48];
    #pragma unroll
    for (int d = 0; d < 48; d++) qreg[d] = qs[qi][d];

    float mcur = -INFINITY, l = 0.0f;
    float acc[12];
    #pragma unroll
    for (int d = 0; d < 12; d++) acc[d] = 0.0f;

    for (int kt = 0; kt < 32; kt++) {
        int k0 = kt * 32;
        __syncthreads();                        // prior tile's vs/ss reads done
        #pragma unroll
        for (int i = 0; i < 6; i++) {           // 32*48 = 1536 = 256*6
            int idx = t + i * 256;
            int ki = idx / 48, d = idx % 48;
            size_t base = (size_t)(b * 1024 + k0 + ki) * 768 + h * 48 + d;
            ks[ki][d] = kv[base];
            vs[ki][d] = kv[base + 384];
        }
        __syncthreads();

        int kb = quad * 8;
        #pragma unroll
        for (int j = 0; j < 8; j++) {
            float dot = 0.0f;
            #pragma unroll
            for (int d = 0; d < 48; d++) dot += qreg[d] * ks[kb + j][d];
            ss[qi][kb + j] = dot;
        }
        __syncthreads();

        float mt;
        if (keep) {
            mt = -INFINITY;
            #pragma unroll
            for (int ki = 0; ki < 32; ki++) mt = fmaxf(mt, ss[qi][ki]);
        } else {
            mt = 0.0f;
        }
        float mnew = fmaxf(mcur, mt);
        float corr = __expf(mcur - mnew);       // exp(-inf)=0 on first tile
        l *= corr;
        #pragma unroll
        for (int d = 0; d < 12; d++) acc[d] *= corr;

        #pragma unroll
        for (int ki = 0; ki < 32; ki++) {
            float sv = keep ? ss[qi][ki] : 0.0f;
            float p = __expf(sv - mnew);
            l += p;
            #pragma unroll
            for (int d = 0; d < 12; d++) acc[d] += p * vs[ki][dbase + d];
        }
        mcur = mnew;
    }

    float rl = 1.0f / l;
    float* po = o + (size_t)(b * 64 + qi) * CDIM + h * 48 + dbase;
    #pragma unroll
    for (int d = 0; d < 12; d++) po[d] = acc[d] * rl;
}

// ---------------- launch ----------------
extern "C" void kernel_launch(void* const* d_in, const int* in_sizes, int n_in,
                              void* d_out, int out_size)
{
    const float*         x    = (const float*)d_in[0];
    const float*         ctx  = (const float*)d_in[1];
    const void*          mask = d_in[2];
    const float* Wq  = (const float*)d_in[3];
    const float* bq  = (const float*)d_in[4];
    const float* Wkv = (const float*)d_in[5];
    const float* bkv = (const float*)d_in[6];
    const float* Wo  = (const float*)d_in[7];
    const float* bo  = (const float*)d_in[8];
    const float* gc  = (const float*)d_in[9];
    const float* bc  = (const float*)d_in[10];
    const float* W1  = (const float*)d_in[11];
    const float* b1  = (const float*)d_in[12];
    const float* W2  = (const float*)d_in[13];
    const float* b2  = (const float*)d_in[14];
    float* out = (float*)d_out;

    float *p_xn, *p_cn, *p_q, *p_kv, *p_o, *p_xn2, *p_h;
    cudaGetSymbolAddress((void**)&p_xn,  g_xn);
    cudaGetSymbolAddress((void**)&p_cn,  g_cn);
    cudaGetSymbolAddress((void**)&p_q,   g_q);
    cudaGetSymbolAddress((void**)&p_kv,  g_kv);
    cudaGetSymbolAddress((void**)&p_o,   g_o);
    cudaGetSymbolAddress((void**)&p_xn2, g_xn2);
    cudaGetSymbolAddress((void**)&p_h,   g_h);

    // 0) mask dtype detection (same stream -> ordered before attention)
    detect_mask_kernel<<<1, 256>>>((const unsigned char*)mask);

    // 1) norms
    ln384_kernel<<<QROWS, 128>>>(x,   p_xn, nullptr, nullptr, 1e-6f);
    ln384_kernel<<<CROWS, 128>>>(ctx, p_cn, gc,      bc,      1e-5f);

    // 2) projections
    gemm_kernel<0><<<dim3(CDIM / 128,      QROWS / 128), 256>>>(
        p_xn, Wq,  bq,  nullptr, p_q,  QROWS, CDIM,     CDIM);
    gemm_kernel<0><<<dim3(2 * CDIM / 128,  CROWS / 128), 256>>>(
        p_cn, Wkv, bkv, nullptr, p_kv, CROWS, 2 * CDIM, CDIM);

    // 3) attention
    attn_kernel<<<192 * HEADS, 256>>>(p_q, p_kv, mask, p_o);

    // 4) output projection + residual -> d_out
    gemm_kernel<2><<<dim3(CDIM / 128, QROWS / 128), 256>>>(
        p_o, Wo, bo, x, out, QROWS, CDIM, CDIM);

    // 5) MLP branch
    ln384_kernel<<<QROWS, 128>>>(out, p_xn2, nullptr, nullptr, 1e-6f);
    gemm_kernel<1><<<dim3(HIDDEN / 128, QROWS / 128), 256>>>(
        p_xn2, W1, b1, nullptr, p_h, QROWS, HIDDEN, CDIM);
    gemm_kernel<2><<<dim3(CDIM / 128, QROWS / 128), 256>>>(
        p_h, W2, b2, out, out, QROWS, CDIM, HIDDEN);
}